// round 2
// baseline (speedup 1.0000x reference)
#include <cuda_runtime.h>
#include <math.h>

// Problem constants (fixed shapes from reference: [2,4,32,64,64])
constexpr int Cc  = 32;            // channels
constexpr int HW  = 4096;          // 64*64 spatial
constexpr int NI  = 8;             // B*L items
constexpr int BPI = 32;            // blocks per item
constexpr int PPB = HW / BPI;      // 128 positions per block
constexpr int TP  = 64;            // positions per smem tile
constexpr int PITCH = 65;          // odd pitch: conflict-free rows AND columns
constexpr int TH1 = 192;           // 3 groups of 64 compute threads

// Scratch: per-block partial 32x32 matrices, [item][block][mat(A,B,M)][32*32]
__device__ float g_scr1[(size_t)NI * BPI * 3 * 1024];
__device__ float g_part[64];

__global__ __launch_bounds__(TH1) void k_partial(const float* __restrict__ S,
                                                 const float* __restrict__ T) {
    __shared__ float sS[Cc][PITCH];
    __shared__ float sT[Cc][PITCH];
    __shared__ float invS[TP], invT[TP];

    const int n    = blockIdx.y;
    const int blk  = blockIdx.x;
    const int tid  = threadIdx.x;
    const float* Sb = S + (size_t)n * Cc * HW;
    const float* Tb = T + (size_t)n * Cc * HW;
    const int pbase = blk * PPB;

    // group 0 -> A (T·T^t), group 1 -> B (S·S^t), group 2 -> M (S·T^t)
    const int grp = tid >> 6;
    const int lt  = tid & 63;
    const int i0  = (lt >> 3) << 2;   // 0,4,...,28
    const int j0  = (lt & 7) << 2;    // 0,4,...,28

    float acc[16];
#pragma unroll
    for (int k = 0; k < 16; ++k) acc[k] = 0.f;

    for (int sub = 0; sub < PPB / TP; ++sub) {
        const int p0 = pbase + sub * TP;

        // Load raw tiles (coalesced: 64 consecutive floats per channel row)
        for (int k = tid; k < Cc * TP; k += TH1) {
            const int c = k >> 6, p = k & 63;
            sS[c][p] = Sb[c * HW + p0 + p];
            sT[c][p] = Tb[c * HW + p0 + p];
        }
        __syncthreads();

        // Per-position channel norms (column access, conflict-free via odd pitch)
        if (tid < TP) {
            float s = 0.f;
#pragma unroll
            for (int c = 0; c < Cc; ++c) { const float v = sS[c][tid]; s += v * v; }
            invS[tid] = 1.f / (sqrtf(s) + 1e-8f);
        } else if (tid < 2 * TP) {
            const int p = tid - TP;
            float s = 0.f;
#pragma unroll
            for (int c = 0; c < Cc; ++c) { const float v = sT[c][p]; s += v * v; }
            invT[p] = 1.f / (sqrtf(s) + 1e-8f);
        }
        __syncthreads();

        // Normalize in smem
        for (int k = tid; k < Cc * TP; k += TH1) {
            const int c = k >> 6, p = k & 63;
            sS[c][p] *= invS[p];
            sT[c][p] *= invT[p];
        }
        __syncthreads();

        // Rank-1 accumulation: each thread owns a 4x4 patch of its matrix
        const float (*Xi)[PITCH] = (grp == 0) ? sT : sS;
        const float (*Xj)[PITCH] = (grp == 1) ? sS : sT;
#pragma unroll 4
        for (int p = 0; p < TP; ++p) {
            float xi[4], xj[4];
#pragma unroll
            for (int r = 0; r < 4; ++r) xi[r] = Xi[i0 + r][p];
#pragma unroll
            for (int r = 0; r < 4; ++r) xj[r] = Xj[j0 + r][p];
#pragma unroll
            for (int r = 0; r < 4; ++r)
#pragma unroll
                for (int q = 0; q < 4; ++q) acc[r * 4 + q] = fmaf(xi[r], xj[q], acc[r * 4 + q]);
        }
        __syncthreads();
    }

    float* out = g_scr1 + (((size_t)n * BPI + blk) * 3 + grp) * 1024;
#pragma unroll
    for (int r = 0; r < 4; ++r)
#pragma unroll
        for (int q = 0; q < 4; ++q)
            out[(i0 + r) * Cc + (j0 + q)] = acc[r * 4 + q];
}

// 64 blocks: (item n, slice s). Sum block-partials per matrix element, square,
// weight (+1 for A,B ; -2 for M), block-reduce.
// 512 threads: 384 active (3 matrices x 128-entry slice), rest contribute 0.
__global__ __launch_bounds__(512) void k_reduce1() {
    const int bid = blockIdx.x;
    const int n = bid >> 3;
    const int s = bid & 7;
    const int t = threadIdx.x;

    float contrib = 0.f;
    if (t < 384) {
        const int mat = t >> 7;          // 0,1,2
        const int e   = s * 128 + (t & 127);
        float v = 0.f;
#pragma unroll 8
        for (int b = 0; b < BPI; ++b)
            v += g_scr1[(((size_t)n * BPI + b) * 3 + mat) * 1024 + e];
        contrib = (mat == 2) ? -2.f * v * v : v * v;
    }

    __shared__ float red[512];
    red[t] = contrib;
    __syncthreads();
    for (int off = 256; off > 0; off >>= 1) {
        if (t < off) red[t] += red[t + off];
        __syncthreads();
    }
    if (t == 0) g_part[bid] = red[0];
}

__global__ __launch_bounds__(64) void k_reduce2(float* __restrict__ out) {
    const int t = threadIdx.x;
    __shared__ float red[64];
    red[t] = g_part[t];
    __syncthreads();
    for (int off = 32; off > 0; off >>= 1) {
        if (t < off) red[t] += red[t + off];
        __syncthreads();
    }
    // loss = total / (HW^2) / (B*L) = total / (16777216 * 8)
    if (t == 0) out[0] = red[0] * (1.f / (16777216.f * 8.f));
}

extern "C" void kernel_launch(void* const* d_in, const int* in_sizes, int n_in,
                              void* d_out, int out_size) {
    const float* S = (const float*)d_in[0];
    const float* T = (const float*)d_in[1];
    (void)in_sizes; (void)n_in; (void)out_size;

    dim3 g1(BPI, NI);
    k_partial<<<g1, TH1>>>(S, T);
    k_reduce1<<<64, 512>>>();
    k_reduce2<<<1, 64>>>((float*)d_out);
}